// round 1
// baseline (speedup 1.0000x reference)
#include <cuda_runtime.h>

#define S_LEN 4096
#define NHEAD 16
#define HD    64
#define WIN   128
#define QT    128
#define KT    32
#define NKT   12            // (QT + 2*WIN) / KT
#define VS_STR 68           // padded V row stride (16B aligned, conflict-light)
#define P_STR  33           // padded P row stride (kills 4-way bank conflict on reads)

struct SmemLayout {
    float Qt[HD][QT];       // 32 KB  (transposed, pre-scaled)
    float Kt[HD][KT];       //  8 KB  (transposed)
    float Vs[KT][VS_STR];   // ~8.5 KB (row-major, padded)
    float P [QT][P_STR];    // ~16.5 KB (exp'd probabilities)
};

__global__ void __launch_bounds__(256, 2)
wattn_kernel(const float* __restrict__ Q, const float* __restrict__ K,
             const float* __restrict__ V, float* __restrict__ O) {
    extern __shared__ float smem_f[];
    SmemLayout* sm = reinterpret_cast<SmemLayout*>(smem_f);

    const int tid = threadIdx.x;
    const int q0  = blockIdx.x * QT;
    const int b   = blockIdx.y / NHEAD;
    const int n   = blockIdx.y - b * NHEAD;
    const size_t base = ((size_t)b * S_LEN * NHEAD + (size_t)n) * (size_t)HD;
    const int rs = NHEAD * HD;   // 1024 floats between consecutive seq positions

    // ---- load Q tile, transposed + scaled by h^-0.5 = 0.125 ----
    {
        const int lane = tid & 31;
        const int w    = tid >> 5;     // 8 warps
        const int dblk = w * 8;
        #pragma unroll
        for (int r = 0; r < 4; r++) {
            const int ql = lane + r * 32;
            const float* src = Q + base + (size_t)(q0 + ql) * rs + dblk;
            const float4 a = *(const float4*)src;
            const float4 c = *(const float4*)(src + 4);
            sm->Qt[dblk + 0][ql] = a.x * 0.125f;
            sm->Qt[dblk + 1][ql] = a.y * 0.125f;
            sm->Qt[dblk + 2][ql] = a.z * 0.125f;
            sm->Qt[dblk + 3][ql] = a.w * 0.125f;
            sm->Qt[dblk + 4][ql] = c.x * 0.125f;
            sm->Qt[dblk + 5][ql] = c.y * 0.125f;
            sm->Qt[dblk + 6][ql] = c.z * 0.125f;
            sm->Qt[dblk + 7][ql] = c.w * 0.125f;
        }
    }

    const int tx = tid & 7;
    const int ty = tid >> 3;
    const int qy = ty * 4;       // this thread's 4 query rows (local)
    const int kx = tx * 4;       // this thread's 4 key cols (score stage)

    float acc[4][8];
    float lsum[4];
    #pragma unroll
    for (int i = 0; i < 4; i++) {
        lsum[i] = 0.0f;
        #pragma unroll
        for (int j = 0; j < 8; j++) acc[i][j] = 0.0f;
    }

    const int kbase0 = q0 - WIN;

    for (int kt = 0; kt < NKT; kt++) {
        __syncthreads();   // previous iteration done with Kt/Vs/P (and Qt written at kt==0)

        // ---- load K tile (transposed) ----
        {
            const int kl   = tid & 31;
            const int w    = tid >> 5;
            const int dblk = w * 8;
            const int gk   = kbase0 + kt * KT + kl;
            float4 a = make_float4(0.f, 0.f, 0.f, 0.f);
            float4 c = make_float4(0.f, 0.f, 0.f, 0.f);
            if (gk >= 0 && gk < S_LEN) {
                const float* src = K + base + (size_t)gk * rs + dblk;
                a = *(const float4*)src;
                c = *(const float4*)(src + 4);
            }
            sm->Kt[dblk + 0][kl] = a.x;
            sm->Kt[dblk + 1][kl] = a.y;
            sm->Kt[dblk + 2][kl] = a.z;
            sm->Kt[dblk + 3][kl] = a.w;
            sm->Kt[dblk + 4][kl] = c.x;
            sm->Kt[dblk + 5][kl] = c.y;
            sm->Kt[dblk + 6][kl] = c.z;
            sm->Kt[dblk + 7][kl] = c.w;
        }
        // ---- load V tile (row-major) ----
        {
            const int kl  = tid >> 3;
            const int off = (tid & 7) * 8;
            const int gk  = kbase0 + kt * KT + kl;
            float4 a = make_float4(0.f, 0.f, 0.f, 0.f);
            float4 c = make_float4(0.f, 0.f, 0.f, 0.f);
            if (gk >= 0 && gk < S_LEN) {
                const float* src = V + base + (size_t)gk * rs + off;
                a = *(const float4*)src;
                c = *(const float4*)(src + 4);
            }
            *(float4*)&sm->Vs[kl][off]     = a;
            *(float4*)&sm->Vs[kl][off + 4] = c;
        }
        __syncthreads();

        // ---- scores: 4q x 4k register tile over 64 dims ----
        float sc[4][4];
        #pragma unroll
        for (int i = 0; i < 4; i++)
            #pragma unroll
            for (int j = 0; j < 4; j++) sc[i][j] = 0.0f;

        #pragma unroll 8
        for (int d = 0; d < HD; d++) {
            const float4 q4 = *(const float4*)&sm->Qt[d][qy];
            const float4 k4 = *(const float4*)&sm->Kt[d][kx];
            const float qv[4] = {q4.x, q4.y, q4.z, q4.w};
            const float kv[4] = {k4.x, k4.y, k4.z, k4.w};
            #pragma unroll
            for (int i = 0; i < 4; i++)
                #pragma unroll
                for (int j = 0; j < 4; j++)
                    sc[i][j] += qv[i] * kv[j];
        }

        // ---- mask + exp -> P ----
        const int gkb = kbase0 + kt * KT + kx;
        #pragma unroll
        for (int i = 0; i < 4; i++) {
            const int gq = q0 + qy + i;
            const int lo = (gq - WIN) > 0 ? (gq - WIN) : 0;
            const int hi = (gq + WIN) < (S_LEN - 1) ? (gq + WIN) : (S_LEN - 1);
            #pragma unroll
            for (int j = 0; j < 4; j++) {
                const int gk = gkb + j;
                const float p = (gk >= lo && gk <= hi) ? __expf(sc[i][j]) : 0.0f;
                sm->P[qy + i][kx + j] = p;
            }
        }
        __syncthreads();

        // ---- PV: acc[4q][8d] += P * V ----
        #pragma unroll 4
        for (int kk = 0; kk < KT; kk++) {
            const float4 vlo = *(const float4*)&sm->Vs[kk][tx * 8];
            const float4 vhi = *(const float4*)&sm->Vs[kk][tx * 8 + 4];
            const float vv[8] = {vlo.x, vlo.y, vlo.z, vlo.w,
                                 vhi.x, vhi.y, vhi.z, vhi.w};
            #pragma unroll
            for (int i = 0; i < 4; i++) {
                const float p = sm->P[qy + i][kk];
                lsum[i] += p;
                #pragma unroll
                for (int j = 0; j < 8; j++) acc[i][j] += p * vv[j];
            }
        }
    }

    // ---- normalize + write out (b, s, nh, h) ----
    #pragma unroll
    for (int i = 0; i < 4; i++) {
        const float inv = 1.0f / lsum[i];
        float* dst = O + base + (size_t)(q0 + qy + i) * rs + tx * 8;
        float4 o0 = make_float4(acc[i][0] * inv, acc[i][1] * inv,
                                acc[i][2] * inv, acc[i][3] * inv);
        float4 o1 = make_float4(acc[i][4] * inv, acc[i][5] * inv,
                                acc[i][6] * inv, acc[i][7] * inv);
        *(float4*)dst       = o0;
        *(float4*)(dst + 4) = o1;
    }
}

extern "C" void kernel_launch(void* const* d_in, const int* in_sizes, int n_in,
                              void* d_out, int out_size) {
    const float* q = (const float*)d_in[0];
    const float* k = (const float*)d_in[1];
    const float* v = (const float*)d_in[2];
    float* out = (float*)d_out;

    const int b = in_sizes[0] / (S_LEN * NHEAD * HD);

    cudaFuncSetAttribute(wattn_kernel,
                         cudaFuncAttributeMaxDynamicSharedMemorySize,
                         (int)sizeof(SmemLayout));

    dim3 grid(S_LEN / QT, b * NHEAD);
    wattn_kernel<<<grid, 256, sizeof(SmemLayout)>>>(q, k, v, out);
}

// round 2
// speedup vs baseline: 2.2485x; 2.2485x over previous
#include <cuda_runtime.h>

#define S_LEN 4096
#define NHEAD 16
#define HD    64
#define WIN   128
#define QT    128
#define KT    32
#define NKT   12
#define P_STR 132            // floats; 528B row, 16B-aligned, bank-shift 4

typedef unsigned long long u64;

struct SmemLayout {
    u64   Qt2[HD/2][QT];     // 32KB  [d-pair][q]      (pre-scaled)
    u64   Kt2[HD/2][KT];     //  8KB  [d-pair][perm(k)]
    u64   Vs2[KT][HD/2];     //  8KB  [k][perm(d-pair)]
    float Pt [KT][P_STR];    // ~17KB [k][q]  (transposed probs)
};

__device__ __forceinline__ u64 pk2(float lo, float hi) {
    u64 r; asm("mov.b64 %0, {%1, %2};" : "=l"(r) : "f"(lo), "f"(hi)); return r;
}
__device__ __forceinline__ void upk2(u64 v, float& lo, float& hi) {
    asm("mov.b64 {%0, %1}, %2;" : "=f"(lo), "=f"(hi) : "l"(v));
}
__device__ __forceinline__ void fma2(u64& d, u64 a, u64 b) {
    asm("fma.rn.f32x2 %0, %1, %2, %3;" : "=l"(d) : "l"(a), "l"(b), "l"(d));
}
// column permutation for 32-entry rows: warp LDS.128 at m*128B + tx*16B is conflict-free
__device__ __forceinline__ int perm32(int j) {
    return ((j >> 1) & 1) * 16 + (j >> 2) * 2 + (j & 1);
}

__global__ void __launch_bounds__(256, 2)
wattn_kernel(const float* __restrict__ Q, const float* __restrict__ K,
             const float* __restrict__ V, float* __restrict__ O) {
    extern __shared__ float smem_f[];
    SmemLayout* sm = reinterpret_cast<SmemLayout*>(smem_f);

    const int tid = threadIdx.x;
    const int q0  = blockIdx.x * QT;
    const int b   = blockIdx.y / NHEAD;
    const int n   = blockIdx.y - b * NHEAD;
    const size_t base = ((size_t)b * S_LEN * NHEAD + (size_t)n) * (size_t)HD;
    const int rs = NHEAD * HD;

    // ---- load Q tile: d-interleaved pairs, transposed, scaled ----
    {
        const int lane = tid & 31;
        const int w    = tid >> 5;
        const int dblk = w * 8;          // dims dblk..dblk+7 -> dd rows dblk/2..+3
        #pragma unroll
        for (int r = 0; r < 4; r++) {
            const int ql = lane + r * 32;
            const float* src = Q + base + (size_t)(q0 + ql) * rs + dblk;
            const float4 a = *(const float4*)src;
            const float4 c = *(const float4*)(src + 4);
            const float s = 0.125f;
            sm->Qt2[(dblk >> 1) + 0][ql] = pk2(a.x * s, a.y * s);
            sm->Qt2[(dblk >> 1) + 1][ql] = pk2(a.z * s, a.w * s);
            sm->Qt2[(dblk >> 1) + 2][ql] = pk2(c.x * s, c.y * s);
            sm->Qt2[(dblk >> 1) + 3][ql] = pk2(c.z * s, c.w * s);
        }
    }

    const int tx = tid & 7;
    const int ty = tid >> 3;
    const int qy = ty * 4;       // 4 query rows
    const int kx = tx * 4;       // 4 key cols (score stage)

    u64 acc2[4][4];              // [q][d-pair]: dims (tx*8+2t, tx*8+2t+1)
    u64 lsA, lsB;                // lane-wise lsum for (q0,q1), (q2,q3)
    const u64 ZERO2 = 0ull;
    const u64 ONE2  = 0x3F8000003F800000ull;
    lsA = lsB = ZERO2;
    #pragma unroll
    for (int i = 0; i < 4; i++)
        #pragma unroll
        for (int t = 0; t < 4; t++) acc2[i][t] = ZERO2;

    const int kbase0 = q0 - WIN;

    for (int kt = 0; kt < NKT; kt++) {
        __syncthreads();   // prev iter done with Kt2/Vs2/Pt

        // ---- load K tile: d-interleaved pairs, permuted key columns ----
        {
            const int kl   = tid & 31;
            const int w    = tid >> 5;
            const int dblk = w * 8;
            const int gk   = kbase0 + kt * KT + kl;
            float4 a = make_float4(0.f, 0.f, 0.f, 0.f);
            float4 c = make_float4(0.f, 0.f, 0.f, 0.f);
            if (gk >= 0 && gk < S_LEN) {
                const float* src = K + base + (size_t)gk * rs + dblk;
                a = *(const float4*)src;
                c = *(const float4*)(src + 4);
            }
            const int pc = perm32(kl);
            sm->Kt2[(dblk >> 1) + 0][pc] = pk2(a.x, a.y);
            sm->Kt2[(dblk >> 1) + 1][pc] = pk2(a.z, a.w);
            sm->Kt2[(dblk >> 1) + 2][pc] = pk2(c.x, c.y);
            sm->Kt2[(dblk >> 1) + 3][pc] = pk2(c.z, c.w);
        }
        // ---- load V tile: d-pairs, permuted d-pair columns ----
        {
            const int kl = tid >> 3;
            const int cc = tid & 7;           // dim block cc*8
            const int gk = kbase0 + kt * KT + kl;
            float4 a = make_float4(0.f, 0.f, 0.f, 0.f);
            float4 c = make_float4(0.f, 0.f, 0.f, 0.f);
            if (gk >= 0 && gk < S_LEN) {
                const float* src = V + base + (size_t)gk * rs + cc * 8;
                a = *(const float4*)src;
                c = *(const float4*)(src + 4);
            }
            sm->Vs2[kl][perm32(cc * 4 + 0)] = pk2(a.x, a.y);
            sm->Vs2[kl][perm32(cc * 4 + 1)] = pk2(a.z, a.w);
            sm->Vs2[kl][perm32(cc * 4 + 2)] = pk2(c.x, c.y);
            sm->Vs2[kl][perm32(cc * 4 + 3)] = pk2(c.z, c.w);
        }
        __syncthreads();

        // ---- scores: 4q x 4k, packed over even/odd dims (FFMA2, zero dup movs) ----
        u64 sc[4][4];
        #pragma unroll
        for (int i = 0; i < 4; i++)
            #pragma unroll
            for (int j = 0; j < 4; j++) sc[i][j] = ZERO2;

        #pragma unroll 8
        for (int dd = 0; dd < HD / 2; dd++) {
            const ulonglong2 qa = *(const ulonglong2*)&sm->Qt2[dd][qy];
            const ulonglong2 qb = *(const ulonglong2*)&sm->Qt2[dd][qy + 2];
            const ulonglong2 ka = *(const ulonglong2*)&sm->Kt2[dd][tx * 2];
            const ulonglong2 kb = *(const ulonglong2*)&sm->Kt2[dd][16 + tx * 2];
            const u64 qv[4] = {qa.x, qa.y, qb.x, qb.y};
            const u64 kv[4] = {ka.x, ka.y, kb.x, kb.y};
            #pragma unroll
            for (int i = 0; i < 4; i++)
                #pragma unroll
                for (int j = 0; j < 4; j++)
                    fma2(sc[i][j], qv[i], kv[j]);
        }

        // ---- reduce pairs, mask, exp -> Pt[k][q] (transposed) ----
        const int gkb = kbase0 + kt * KT + kx;
        #pragma unroll
        for (int i = 0; i < 4; i++) {
            const int gq = q0 + qy + i;
            const int lo = (gq - WIN) > 0 ? (gq - WIN) : 0;
            const int hi = (gq + WIN) < (S_LEN - 1) ? (gq + WIN) : (S_LEN - 1);
            #pragma unroll
            for (int j = 0; j < 4; j++) {
                float e, o;
                upk2(sc[i][j], e, o);
                const float s = e + o;
                const int gk = gkb + j;
                const float p = (gk >= lo && gk <= hi) ? __expf(s) : 0.0f;
                sm->Pt[kx + j][qy + i] = p;
            }
        }
        __syncthreads();

        // ---- PV: acc2[q][d-pair] += dup(p) * vpair ----
        #pragma unroll 4
        for (int kk = 0; kk < KT; kk++) {
            const ulonglong2 pu = *(const ulonglong2*)&sm->Pt[kk][qy];
            const ulonglong2 va = *(const ulonglong2*)&sm->Vs2[kk][tx * 2];
            const ulonglong2 vb = *(const ulonglong2*)&sm->Vs2[kk][16 + tx * 2];
            fma2(lsA, pu.x, ONE2);           // lsum lanes (q0,q1)
            fma2(lsB, pu.y, ONE2);           // lsum lanes (q2,q3)
            float p0, p1, p2, p3;
            upk2(pu.x, p0, p1);
            upk2(pu.y, p2, p3);
            const u64 pd[4] = {pk2(p0, p0), pk2(p1, p1), pk2(p2, p2), pk2(p3, p3)};
            const u64 vv[4] = {va.x, va.y, vb.x, vb.y};
            #pragma unroll
            for (int i = 0; i < 4; i++)
                #pragma unroll
                for (int t = 0; t < 4; t++)
                    fma2(acc2[i][t], pd[i], vv[t]);
        }
    }

    // ---- normalize + write out (b, s, nh, h) ----
    float ls[4];
    upk2(lsA, ls[0], ls[1]);
    upk2(lsB, ls[2], ls[3]);
    #pragma unroll
    for (int i = 0; i < 4; i++) {
        const float inv = 1.0f / ls[i];
        float a0, a1, a2, a3, a4, a5, a6, a7;
        upk2(acc2[i][0], a0, a1);
        upk2(acc2[i][1], a2, a3);
        upk2(acc2[i][2], a4, a5);
        upk2(acc2[i][3], a6, a7);
        float* dst = O + base + (size_t)(q0 + qy + i) * rs + tx * 8;
        *(float4*)dst       = make_float4(a0 * inv, a1 * inv, a2 * inv, a3 * inv);
        *(float4*)(dst + 4) = make_float4(a4 * inv, a5 * inv, a6 * inv, a7 * inv);
    }
}

extern "C" void kernel_launch(void* const* d_in, const int* in_sizes, int n_in,
                              void* d_out, int out_size) {
    const float* q = (const float*)d_in[0];
    const float* k = (const float*)d_in[1];
    const float* v = (const float*)d_in[2];
    float* out = (float*)d_out;

    const int b = in_sizes[0] / (S_LEN * NHEAD * HD);

    cudaFuncSetAttribute(wattn_kernel,
                         cudaFuncAttributeMaxDynamicSharedMemorySize,
                         (int)sizeof(SmemLayout));

    dim3 grid(S_LEN / QT, b * NHEAD);
    wattn_kernel<<<grid, 256, sizeof(SmemLayout)>>>(q, k, v, out);
}

// round 4
// speedup vs baseline: 5.4552x; 2.4262x over previous
#include <cuda_runtime.h>
#include <cuda_bf16.h>
#include <cstdint>

#define S_LEN 4096
#define NHEAD 16
#define HD    64
#define WIN   128
#define QT    64
#define KT    64
#define NKT   5        // (QT + 2*WIN) / KT

// ---- static smem byte offsets (tiles: 64 rows x 128 bytes, XOR-swizzled) ----
#define SM_QHI 0
#define SM_QLO 8192
#define SM_KHI 16384
#define SM_KLO 24576
#define SM_VHI 32768
#define SM_VLO 40960
#define SM_TOTAL 49152

__device__ __forceinline__ uint32_t swz(uint32_t o) {
    return o ^ (((o >> 7) & 7u) << 4);
}
__device__ __forceinline__ uint32_t smem_u32(const void* p) {
    uint32_t a;
    asm("{ .reg .u64 t; cvta.to.shared.u64 t, %1; cvt.u32.u64 %0, t; }" : "=r"(a) : "l"(p));
    return a;
}
__device__ __forceinline__ void ldsm4(uint32_t addr, uint32_t* r) {
    asm volatile("ldmatrix.sync.aligned.m8n8.x4.shared.b16 {%0,%1,%2,%3}, [%4];"
        : "=r"(r[0]), "=r"(r[1]), "=r"(r[2]), "=r"(r[3]) : "r"(addr));
}
__device__ __forceinline__ void ldsm4t(uint32_t addr, uint32_t* r) {
    asm volatile("ldmatrix.sync.aligned.m8n8.x4.trans.shared.b16 {%0,%1,%2,%3}, [%4];"
        : "=r"(r[0]), "=r"(r[1]), "=r"(r[2]), "=r"(r[3]) : "r"(addr));
}
__device__ __forceinline__ void mma_bf16(float* c, const uint32_t* a, uint32_t b0, uint32_t b1) {
    asm volatile("mma.sync.aligned.m16n8k16.row.col.f32.bf16.bf16.f32 "
        "{%0,%1,%2,%3}, {%4,%5,%6,%7}, {%8,%9}, {%0,%1,%2,%3};"
        : "+f"(c[0]), "+f"(c[1]), "+f"(c[2]), "+f"(c[3])
        : "r"(a[0]), "r"(a[1]), "r"(a[2]), "r"(a[3]), "r"(b0), "r"(b1));
}
// pack two floats -> bf16x2 (lo half = first arg)
__device__ __forceinline__ uint32_t pack_bf(float lo, float hi) {
    uint32_t r;
    asm("cvt.rn.bf16x2.f32 %0, %1, %2;" : "=r"(r) : "f"(hi), "f"(lo));
    return r;
}
// split (x0,x1) into bf16 hi pair + bf16 residual pair
__device__ __forceinline__ void split_pair(float x0, float x1, uint32_t& h, uint32_t& l) {
    h = pack_bf(x0, x1);
    const float h0 = __uint_as_float(h << 16);
    const float h1 = __uint_as_float(h & 0xFFFF0000u);
    l = pack_bf(x0 - h0, x1 - h1);
}

__global__ void __launch_bounds__(128)
wattn_mma_kernel(const float* __restrict__ Q, const float* __restrict__ K,
                 const float* __restrict__ V, float* __restrict__ O) {
    __shared__ char smem[SM_TOTAL];
    const uint32_t sb = smem_u32(smem);

    const int tid  = threadIdx.x;
    const int wid  = tid >> 5;
    const int lane = tid & 31;

    const int q0 = blockIdx.x * QT;
    const int b  = blockIdx.y >> 4;
    const int n  = blockIdx.y & 15;
    const size_t base = ((size_t)b * S_LEN * NHEAD + (size_t)n) * (size_t)HD;
    const int rs = NHEAD * HD;

    // ---- load Q tile -> bf16 hi/lo, swizzled [row][dim] ----
    {
        const int pc = tid & 31;         // dim-pair 0..31
        const int r0 = tid >> 5;         // row base
        #pragma unroll
        for (int i = 0; i < 16; i++) {
            const int r = r0 + i * 4;
            const float2 x = *(const float2*)(Q + base + (size_t)(q0 + r) * rs + pc * 2);
            uint32_t h, l;
            split_pair(x.x * 0.125f, x.y * 0.125f, h, l);
            const uint32_t off = swz((uint32_t)(r * 128 + pc * 4));
            *(uint32_t*)(smem + SM_QHI + off) = h;
            *(uint32_t*)(smem + SM_QLO + off) = l;
        }
    }
    __syncthreads();

    // ---- Q a-frags (persistent): 4 k-steps x 4 regs, hi & lo ----
    uint32_t qh[4][4], ql[4][4];
    {
        const int row = wid * 16 + (lane & 15);
        const int dsel = ((lane >> 4) & 1) * 16;
        #pragma unroll
        for (int ks = 0; ks < 4; ks++) {
            const uint32_t off = swz((uint32_t)(row * 128 + ks * 32 + dsel));
            ldsm4(sb + SM_QHI + off, qh[ks]);
            ldsm4(sb + SM_QLO + off, ql[ks]);
        }
    }

    const int g = lane >> 2;
    const int t = lane & 3;
    const int gq0 = q0 + wid * 16 + g;
    const int gq1 = gq0 + 8;
    const int wlo0 = (gq0 - WIN) > 0 ? (gq0 - WIN) : 0;
    const int whi0 = (gq0 + WIN) < (S_LEN - 1) ? (gq0 + WIN) : (S_LEN - 1);
    const int wlo1 = (gq1 - WIN) > 0 ? (gq1 - WIN) : 0;
    const int whi1 = (gq1 + WIN) < (S_LEN - 1) ? (gq1 + WIN) : (S_LEN - 1);

    float oc[8][4];
    #pragma unroll
    for (int i = 0; i < 8; i++)
        #pragma unroll
        for (int j = 0; j < 4; j++) oc[i][j] = 0.0f;
    float ls0 = 0.0f, ls1 = 0.0f;

    // lane-invariant pieces of ldmatrix addressing
    const int kb_key  = (lane & 7) + ((lane & 16) ? 8 : 0);   // QK B: key within 16-group
    const int kb_dsel = (lane & 8) ? 16 : 0;                  // QK B: dim-byte select
    const int vb_key  = (lane & 7) + ((lane & 8) ? 8 : 0);    // PV B: key within 16-group
    const int vb_dsel = (lane & 16) ? 16 : 0;                 // PV B: dim-byte select

    for (int kt = 0; kt < NKT; kt++) {
        const int kbase = q0 - WIN + kt * KT;

        __syncthreads();     // previous tile's compute done

        // ---- load K,V tiles -> bf16 hi/lo, swizzled [key][dim] ----
        {
            const int pc = tid & 31;
            const int r0 = tid >> 5;
            #pragma unroll
            for (int i = 0; i < 16; i++) {
                const int r = r0 + i * 4;
                const int gk = kbase + r;
                float2 xk = make_float2(0.f, 0.f), xv = make_float2(0.f, 0.f);
                if (gk >= 0 && gk < S_LEN) {
                    xk = *(const float2*)(K + base + (size_t)gk * rs + pc * 2);
                    xv = *(const float2*)(V + base + (size_t)gk * rs + pc * 2);
                }
                uint32_t h, l;
                const uint32_t off = swz((uint32_t)(r * 128 + pc * 4));
                split_pair(xk.x, xk.y, h, l);
                *(uint32_t*)(smem + SM_KHI + off) = h;
                *(uint32_t*)(smem + SM_KLO + off) = l;
                split_pair(xv.x, xv.y, h, l);
                *(uint32_t*)(smem + SM_VHI + off) = h;
                *(uint32_t*)(smem + SM_VLO + off) = l;
            }
        }
        __syncthreads();

        // ---- QK^T: S[16q x 64k], 3-way split ----
        float sc[8][4];
        #pragma unroll
        for (int i = 0; i < 8; i++)
            #pragma unroll
            for (int j = 0; j < 4; j++) sc[i][j] = 0.0f;

        #pragma unroll
        for (int ks = 0; ks < 4; ks++) {
            #pragma unroll
            for (int ng = 0; ng < 4; ng++) {
                const uint32_t off = swz((uint32_t)((ng * 16 + kb_key) * 128 + ks * 32 + kb_dsel));
                uint32_t bh[4], bl[4];
                ldsm4(sb + SM_KHI + off, bh);
                ldsm4(sb + SM_KLO + off, bl);
                mma_bf16(sc[2 * ng],     qh[ks], bh[0], bh[1]);
                mma_bf16(sc[2 * ng],     qh[ks], bl[0], bl[1]);
                mma_bf16(sc[2 * ng],     ql[ks], bh[0], bh[1]);
                mma_bf16(sc[2 * ng + 1], qh[ks], bh[2], bh[3]);
                mma_bf16(sc[2 * ng + 1], qh[ks], bl[2], bl[3]);
                mma_bf16(sc[2 * ng + 1], ql[ks], bh[2], bh[3]);
            }
        }

        // ---- mask + exp (in place, fp32) ----
        #pragma unroll
        for (int nt = 0; nt < 8; nt++) {
            const int k0 = kbase + nt * 8 + 2 * t;
            const int k1 = k0 + 1;
            const float p0 = (k0 >= wlo0 && k0 <= whi0) ? __expf(sc[nt][0]) : 0.0f;
            const float p1 = (k1 >= wlo0 && k1 <= whi0) ? __expf(sc[nt][1]) : 0.0f;
            const float p2 = (k0 >= wlo1 && k0 <= whi1) ? __expf(sc[nt][2]) : 0.0f;
            const float p3 = (k1 >= wlo1 && k1 <= whi1) ? __expf(sc[nt][3]) : 0.0f;
            ls0 += p0 + p1;
            ls1 += p2 + p3;
            sc[nt][0] = p0; sc[nt][1] = p1; sc[nt][2] = p2; sc[nt][3] = p3;
        }

        // ---- PV: O += P * V, P a-frags built from S c-frags (register reuse) ----
        #pragma unroll
        for (int s = 0; s < 4; s++) {
            uint32_t phi[4], plo[4];
            split_pair(sc[2 * s][0],     sc[2 * s][1],     phi[0], plo[0]);
            split_pair(sc[2 * s][2],     sc[2 * s][3],     phi[1], plo[1]);
            split_pair(sc[2 * s + 1][0], sc[2 * s + 1][1], phi[2], plo[2]);
            split_pair(sc[2 * s + 1][2], sc[2 * s + 1][3], phi[3], plo[3]);
            #pragma unroll
            for (int dg = 0; dg < 4; dg++) {
                const uint32_t off = swz((uint32_t)((s * 16 + vb_key) * 128 + dg * 32 + vb_dsel));
                uint32_t vh[4], vl[4];
                ldsm4t(sb + SM_VHI + off, vh);
                ldsm4t(sb + SM_VLO + off, vl);
                mma_bf16(oc[2 * dg],     phi, vh[0], vh[1]);
                mma_bf16(oc[2 * dg],     phi, vl[0], vl[1]);
                mma_bf16(oc[2 * dg],     plo, vh[0], vh[1]);
                mma_bf16(oc[2 * dg + 1], phi, vh[2], vh[3]);
                mma_bf16(oc[2 * dg + 1], phi, vl[2], vl[3]);
                mma_bf16(oc[2 * dg + 1], plo, vh[2], vh[3]);
            }
        }
    }

    // ---- reduce lsum across the quad (lanes sharing a row) ----
    ls0 += __shfl_xor_sync(0xFFFFFFFF, ls0, 1);
    ls0 += __shfl_xor_sync(0xFFFFFFFF, ls0, 2);
    ls1 += __shfl_xor_sync(0xFFFFFFFF, ls1, 1);
    ls1 += __shfl_xor_sync(0xFFFFFFFF, ls1, 2);
    const float inv0 = 1.0f / ls0;
    const float inv1 = 1.0f / ls1;

    // ---- write output: O[b][gq][n][d] ----
    float* dst0 = O + base + (size_t)gq0 * rs;
    float* dst1 = O + base + (size_t)gq1 * rs;
    #pragma unroll
    for (int nt = 0; nt < 8; nt++) {
        const int d = nt * 8 + 2 * t;
        *(float2*)(dst0 + d) = make_float2(oc[nt][0] * inv0, oc[nt][1] * inv0);
        *(float2*)(dst1 + d) = make_float2(oc[nt][2] * inv1, oc[nt][3] * inv1);
    }
}

extern "C" void kernel_launch(void* const* d_in, const int* in_sizes, int n_in,
                              void* d_out, int out_size) {
    const float* q = (const float*)d_in[0];
    const float* k = (const float*)d_in[1];
    const float* v = (const float*)d_in[2];
    float* out = (float*)d_out;

    const int b = in_sizes[0] / (S_LEN * NHEAD * HD);

    dim3 grid(S_LEN / QT, b * NHEAD);
    wattn_mma_kernel<<<grid, 128>>>(q, k, v, out);
}

// round 5
// speedup vs baseline: 7.2653x; 1.3318x over previous
#include <cuda_runtime.h>
#include <cuda_bf16.h>
#include <cstdint>

#define S_LEN 4096
#define NHEAD 16
#define HD    64
#define WIN   128
#define QT    64
#define KT    64
#define NKT   5        // (QT + 2*WIN) / KT

// ---- static smem byte offsets (tiles: 64 rows x 128 bytes, XOR-swizzled) ----
#define SM_QHI 0
#define SM_QLO 8192
#define SM_KHI 16384
#define SM_KLO 24576
#define SM_VHI 32768
#define SM_VLO 40960
#define SM_TOTAL 49152

// 0.125 * log2(e)
#define QSCALE 0.1803368801111204f

__device__ __forceinline__ uint32_t swz(uint32_t o) {
    return o ^ (((o >> 7) & 7u) << 4);
}
__device__ __forceinline__ uint32_t smem_u32(const void* p) {
    uint32_t a;
    asm("{ .reg .u64 t; cvta.to.shared.u64 t, %1; cvt.u32.u64 %0, t; }" : "=r"(a) : "l"(p));
    return a;
}
__device__ __forceinline__ void ldsm4(uint32_t addr, uint32_t* r) {
    asm volatile("ldmatrix.sync.aligned.m8n8.x4.shared.b16 {%0,%1,%2,%3}, [%4];"
        : "=r"(r[0]), "=r"(r[1]), "=r"(r[2]), "=r"(r[3]) : "r"(addr));
}
__device__ __forceinline__ void ldsm4t(uint32_t addr, uint32_t* r) {
    asm volatile("ldmatrix.sync.aligned.m8n8.x4.trans.shared.b16 {%0,%1,%2,%3}, [%4];"
        : "=r"(r[0]), "=r"(r[1]), "=r"(r[2]), "=r"(r[3]) : "r"(addr));
}
__device__ __forceinline__ void mma_bf16(float* c, const uint32_t* a, uint32_t b0, uint32_t b1) {
    asm volatile("mma.sync.aligned.m16n8k16.row.col.f32.bf16.bf16.f32 "
        "{%0,%1,%2,%3}, {%4,%5,%6,%7}, {%8,%9}, {%0,%1,%2,%3};"
        : "+f"(c[0]), "+f"(c[1]), "+f"(c[2]), "+f"(c[3])
        : "r"(a[0]), "r"(a[1]), "r"(a[2]), "r"(a[3]), "r"(b0), "r"(b1));
}
__device__ __forceinline__ uint32_t pack_bf(float lo, float hi) {
    uint32_t r;
    asm("cvt.rn.bf16x2.f32 %0, %1, %2;" : "=r"(r) : "f"(hi), "f"(lo));
    return r;
}
__device__ __forceinline__ void split_pair(float x0, float x1, uint32_t& h, uint32_t& l) {
    h = pack_bf(x0, x1);
    const float h0 = __uint_as_float(h << 16);
    const float h1 = __uint_as_float(h & 0xFFFF0000u);
    l = pack_bf(x0 - h0, x1 - h1);
}
__device__ __forceinline__ float ex2(float x) {
    float r;
    asm("ex2.approx.f32 %0, %1;" : "=f"(r) : "f"(x));
    return r;
}

__global__ void __launch_bounds__(128, 3)
wattn_mma_kernel(const float* __restrict__ Q, const float* __restrict__ K,
                 const float* __restrict__ V, float* __restrict__ O) {
    __shared__ char smem[SM_TOTAL];
    const uint32_t sb = smem_u32(smem);

    const int tid  = threadIdx.x;
    const int wid  = tid >> 5;
    const int lane = tid & 31;

    const int q0 = blockIdx.x * QT;
    const int b  = blockIdx.y >> 4;
    const int n  = blockIdx.y & 15;
    const size_t base = ((size_t)b * S_LEN * NHEAD + (size_t)n) * (size_t)HD;
    const int rs = NHEAD * HD;

    const int pc4 = tid & 15;        // dim-quad 0..15 (4 dims = 8 bytes bf16)
    const int r0  = tid >> 4;        // row base 0..7

    // ---- load Q tile -> bf16 hi/lo, swizzled [row][dim], scaled by 0.125*log2e ----
    {
        #pragma unroll
        for (int i = 0; i < 8; i++) {
            const int r = r0 + i * 8;
            const float4 x = *(const float4*)(Q + base + (size_t)(q0 + r) * rs + pc4 * 4);
            uint32_t h0, l0, h1, l1;
            split_pair(x.x * QSCALE, x.y * QSCALE, h0, l0);
            split_pair(x.z * QSCALE, x.w * QSCALE, h1, l1);
            const uint32_t off = swz((uint32_t)(r * 128 + pc4 * 8));
            *(uint2*)(smem + SM_QHI + off) = make_uint2(h0, h1);
            *(uint2*)(smem + SM_QLO + off) = make_uint2(l0, l1);
        }
    }

    const int g = lane >> 2;
    const int t = lane & 3;
    const int gq0 = q0 + wid * 16 + g;
    const int gq1 = gq0 + 8;
    const int wlo0 = (gq0 - WIN) > 0 ? (gq0 - WIN) : 0;
    const int whi0 = (gq0 + WIN) < (S_LEN - 1) ? (gq0 + WIN) : (S_LEN - 1);
    const int wlo1 = (gq1 - WIN) > 0 ? (gq1 - WIN) : 0;
    const int whi1 = (gq1 + WIN) < (S_LEN - 1) ? (gq1 + WIN) : (S_LEN - 1);

    float oc[8][4];
    #pragma unroll
    for (int i = 0; i < 8; i++)
        #pragma unroll
        for (int j = 0; j < 4; j++) oc[i][j] = 0.0f;
    float ls0 = 0.0f, ls1 = 0.0f;

    // ldmatrix addressing (lane-dependent, loop-invariant)
    const int qa_row  = wid * 16 + (lane & 15);               // Q a-frag row
    const int qa_dsel = ((lane >> 4) & 1) * 16;               // Q a-frag byte sel
    const int kb_key  = (lane & 7) + ((lane & 16) ? 8 : 0);   // QK B: key in 16-group
    const int kb_dsel = (lane & 8) ? 16 : 0;
    const int vb_key  = (lane & 7) + ((lane & 8) ? 8 : 0);    // PV B: key in 16-group
    const int vb_dsel = (lane & 16) ? 16 : 0;

    for (int kt = 0; kt < NKT; kt++) {
        const int kbase = q0 - WIN + kt * KT;

        __syncthreads();     // previous tile's compute done

        // ---- load K,V tiles -> bf16 hi/lo, swizzled [key][dim] ----
        #pragma unroll
        for (int i = 0; i < 8; i++) {
            const int r = r0 + i * 8;
            const int gk = kbase + r;
            float4 xk = make_float4(0.f, 0.f, 0.f, 0.f);
            float4 xv = make_float4(0.f, 0.f, 0.f, 0.f);
            if (gk >= 0 && gk < S_LEN) {
                xk = *(const float4*)(K + base + (size_t)gk * rs + pc4 * 4);
                xv = *(const float4*)(V + base + (size_t)gk * rs + pc4 * 4);
            }
            const uint32_t off = swz((uint32_t)(r * 128 + pc4 * 8));
            uint32_t h0, l0, h1, l1;
            split_pair(xk.x, xk.y, h0, l0);
            split_pair(xk.z, xk.w, h1, l1);
            *(uint2*)(smem + SM_KHI + off) = make_uint2(h0, h1);
            *(uint2*)(smem + SM_KLO + off) = make_uint2(l0, l1);
            split_pair(xv.x, xv.y, h0, l0);
            split_pair(xv.z, xv.w, h1, l1);
            *(uint2*)(smem + SM_VHI + off) = make_uint2(h0, h1);
            *(uint2*)(smem + SM_VLO + off) = make_uint2(l0, l1);
        }
        __syncthreads();

        // ---- QK^T: S[16q x 64k], 3-way bf16 split ----
        float sc[8][4];
        #pragma unroll
        for (int i = 0; i < 8; i++)
            #pragma unroll
            for (int j = 0; j < 4; j++) sc[i][j] = 0.0f;

        #pragma unroll
        for (int ks = 0; ks < 4; ks++) {
            uint32_t qh[4], ql[4];
            const uint32_t qoff = swz((uint32_t)(qa_row * 128 + ks * 32 + qa_dsel));
            ldsm4(sb + SM_QHI + qoff, qh);
            ldsm4(sb + SM_QLO + qoff, ql);
            #pragma unroll
            for (int ng = 0; ng < 4; ng++) {
                const uint32_t off = swz((uint32_t)((ng * 16 + kb_key) * 128 + ks * 32 + kb_dsel));
                uint32_t bh[4], bl[4];
                ldsm4(sb + SM_KHI + off, bh);
                ldsm4(sb + SM_KLO + off, bl);
                mma_bf16(sc[2 * ng],     qh, bh[0], bh[1]);
                mma_bf16(sc[2 * ng],     qh, bl[0], bl[1]);
                mma_bf16(sc[2 * ng],     ql, bh[0], bh[1]);
                mma_bf16(sc[2 * ng + 1], qh, bh[2], bh[3]);
                mma_bf16(sc[2 * ng + 1], qh, bl[2], bl[3]);
                mma_bf16(sc[2 * ng + 1], ql, bh[2], bh[3]);
            }
        }

        // ---- mask + exp2 (scores already include log2e) ----
        #pragma unroll
        for (int nt = 0; nt < 8; nt++) {
            const int k0 = kbase + nt * 8 + 2 * t;
            const int k1 = k0 + 1;
            const float p0 = (k0 >= wlo0 && k0 <= whi0) ? ex2(sc[nt][0]) : 0.0f;
            const float p1 = (k1 >= wlo0 && k1 <= whi0) ? ex2(sc[nt][1]) : 0.0f;
            const float p2 = (k0 >= wlo1 && k0 <= whi1) ? ex2(sc[nt][2]) : 0.0f;
            const float p3 = (k1 >= wlo1 && k1 <= whi1) ? ex2(sc[nt][3]) : 0.0f;
            ls0 += p0 + p1;
            ls1 += p2 + p3;
            sc[nt][0] = p0; sc[nt][1] = p1; sc[nt][2] = p2; sc[nt][3] = p3;
        }

        // ---- PV: O += P * V, P a-frags from S c-frags (register reuse) ----
        #pragma unroll
        for (int s = 0; s < 4; s++) {
            uint32_t phi[4], plo[4];
            split_pair(sc[2 * s][0],     sc[2 * s][1],     phi[0], plo[0]);
            split_pair(sc[2 * s][2],     sc[2 * s][3],     phi[1], plo[1]);
            split_pair(sc[2 * s + 1][0], sc[2 * s + 1][1], phi[2], plo[2]);
            split_pair(sc[2 * s + 1][2], sc[2 * s + 1][3], phi[3], plo[3]);
            #pragma unroll
            for (int dg = 0; dg < 4; dg++) {
                const uint32_t off = swz((uint32_t)((s * 16 + vb_key) * 128 + dg * 32 + vb_dsel));
                uint32_t vh[4], vl[4];
                ldsm4t(sb + SM_VHI + off, vh);
                ldsm4t(sb + SM_VLO + off, vl);
                mma_bf16(oc[2 * dg],     phi, vh[0], vh[1]);
                mma_bf16(oc[2 * dg],     phi, vl[0], vl[1]);
                mma_bf16(oc[2 * dg],     plo, vh[0], vh[1]);
                mma_bf16(oc[2 * dg + 1], phi, vh[2], vh[3]);
                mma_bf16(oc[2 * dg + 1], phi, vl[2], vl[3]);
                mma_bf16(oc[2 * dg + 1], plo, vh[2], vh[3]);
            }
        }
    }

    // ---- reduce lsum across the quad ----
    ls0 += __shfl_xor_sync(0xFFFFFFFF, ls0, 1);
    ls0 += __shfl_xor_sync(0xFFFFFFFF, ls0, 2);
    ls1 += __shfl_xor_sync(0xFFFFFFFF, ls1, 1);
    ls1 += __shfl_xor_sync(0xFFFFFFFF, ls1, 2);
    const float inv0 = 1.0f / ls0;
    const float inv1 = 1.0f / ls1;

    // ---- write output: O[b][gq][n][d] ----
    float* dst0 = O + base + (size_t)gq0 * rs;
    float* dst1 = O + base + (size_t)gq1 * rs;
    #pragma unroll
    for (int nt = 0; nt < 8; nt++) {
        const int d = nt * 8 + 2 * t;
        *(float2*)(dst0 + d) = make_float2(oc[nt][0] * inv0, oc[nt][1] * inv0);
        *(float2*)(dst1 + d) = make_float2(oc[nt][2] * inv1, oc[nt][3] * inv1);
    }
}

extern "C" void kernel_launch(void* const* d_in, const int* in_sizes, int n_in,
                              void* d_out, int out_size) {
    const float* q = (const float*)d_in[0];
    const float* k = (const float*)d_in[1];
    const float* v = (const float*)d_in[2];
    float* out = (float*)d_out;

    const int b = in_sizes[0] / (S_LEN * NHEAD * HD);

    dim3 grid(S_LEN / QT, b * NHEAD);
    wattn_mma_kernel<<<grid, 128>>>(q, k, v, out);
}

// round 6
// speedup vs baseline: 8.0647x; 1.1100x over previous
#include <cuda_runtime.h>
#include <cuda_bf16.h>
#include <cuda_fp16.h>
#include <cstdint>

#define S_LEN 4096
#define NHEAD 16
#define HD    64
#define WIN   128
#define QT    64
#define KT    64
#define NKT   5        // (QT + 2*WIN) / KT

// ---- static smem byte offsets (tiles: 64 rows x 128 bytes, XOR-swizzled) ----
#define SM_QHI 0
#define SM_QLO 8192
#define SM_KHI 16384
#define SM_KLO 24576
#define SM_VHI 32768
#define SM_VLO 40960
#define SM_TOTAL 49152

// 0.125 * log2(e)
#define QSCALE 0.1803368801111204f

__device__ __forceinline__ uint32_t swz(uint32_t o) {
    return o ^ (((o >> 7) & 7u) << 4);
}
__device__ __forceinline__ uint32_t smem_u32(const void* p) {
    uint32_t a;
    asm("{ .reg .u64 t; cvta.to.shared.u64 t, %1; cvt.u32.u64 %0, t; }" : "=r"(a) : "l"(p));
    return a;
}
__device__ __forceinline__ void ldsm4(uint32_t addr, uint32_t* r) {
    asm volatile("ldmatrix.sync.aligned.m8n8.x4.shared.b16 {%0,%1,%2,%3}, [%4];"
        : "=r"(r[0]), "=r"(r[1]), "=r"(r[2]), "=r"(r[3]) : "r"(addr));
}
__device__ __forceinline__ void ldsm4t(uint32_t addr, uint32_t* r) {
    asm volatile("ldmatrix.sync.aligned.m8n8.x4.trans.shared.b16 {%0,%1,%2,%3}, [%4];"
        : "=r"(r[0]), "=r"(r[1]), "=r"(r[2]), "=r"(r[3]) : "r"(addr));
}
__device__ __forceinline__ void mma_bf16(float* c, const uint32_t* a, uint32_t b0, uint32_t b1) {
    asm volatile("mma.sync.aligned.m16n8k16.row.col.f32.bf16.bf16.f32 "
        "{%0,%1,%2,%3}, {%4,%5,%6,%7}, {%8,%9}, {%0,%1,%2,%3};"
        : "+f"(c[0]), "+f"(c[1]), "+f"(c[2]), "+f"(c[3])
        : "r"(a[0]), "r"(a[1]), "r"(a[2]), "r"(a[3]), "r"(b0), "r"(b1));
}
__device__ __forceinline__ void mma_f16(float* c, const uint32_t* a, uint32_t b0, uint32_t b1) {
    asm volatile("mma.sync.aligned.m16n8k16.row.col.f32.f16.f16.f32 "
        "{%0,%1,%2,%3}, {%4,%5,%6,%7}, {%8,%9}, {%0,%1,%2,%3};"
        : "+f"(c[0]), "+f"(c[1]), "+f"(c[2]), "+f"(c[3])
        : "r"(a[0]), "r"(a[1]), "r"(a[2]), "r"(a[3]), "r"(b0), "r"(b1));
}
__device__ __forceinline__ uint32_t pack_bf(float lo, float hi) {
    uint32_t r;
    asm("cvt.rn.bf16x2.f32 %0, %1, %2;" : "=r"(r) : "f"(hi), "f"(lo));
    return r;
}
__device__ __forceinline__ void split_bf(float x0, float x1, uint32_t& h, uint32_t& l) {
    h = pack_bf(x0, x1);
    const float h0 = __uint_as_float(h << 16);
    const float h1 = __uint_as_float(h & 0xFFFF0000u);
    l = pack_bf(x0 - h0, x1 - h1);
}
__device__ __forceinline__ uint32_t pack_h2(float lo, float hi) {
    __half2 h = __floats2half2_rn(lo, hi);
    return *reinterpret_cast<uint32_t*>(&h);
}
__device__ __forceinline__ void split_h2(float x0, float x1, uint32_t& h, uint32_t& l) {
    h = pack_h2(x0, x1);
    __half2 hh = *reinterpret_cast<__half2*>(&h);
    float2 f = __half22float2(hh);
    l = pack_h2(x0 - f.x, x1 - f.y);
}
__device__ __forceinline__ float ex2(float x) {
    float r;
    asm("ex2.approx.f32 %0, %1;" : "=f"(r) : "f"(x));
    return r;
}

__global__ void __launch_bounds__(128, 3)
wattn_mma_kernel(const float* __restrict__ Q, const float* __restrict__ K,
                 const float* __restrict__ V, float* __restrict__ O) {
    __shared__ char smem[SM_TOTAL];
    const uint32_t sb = smem_u32(smem);

    const int tid  = threadIdx.x;
    const int wid  = tid >> 5;
    const int lane = tid & 31;

    const int q0 = blockIdx.x * QT;
    const int b  = blockIdx.y >> 4;
    const int n  = blockIdx.y & 15;
    const size_t base = ((size_t)b * S_LEN * NHEAD + (size_t)n) * (size_t)HD;
    const int rs = NHEAD * HD;

    const int pc4 = tid & 15;        // dim-quad 0..15 (4 dims = 8 bytes)
    const int r0  = tid >> 4;        // row base 0..7

    // ---- load Q tile -> bf16 hi/lo, swizzled [row][dim], scaled by 0.125*log2e ----
    {
        #pragma unroll
        for (int i = 0; i < 8; i++) {
            const int r = r0 + i * 8;
            const float4 x = *(const float4*)(Q + base + (size_t)(q0 + r) * rs + pc4 * 4);
            uint32_t h0, l0, h1, l1;
            split_bf(x.x * QSCALE, x.y * QSCALE, h0, l0);
            split_bf(x.z * QSCALE, x.w * QSCALE, h1, l1);
            const uint32_t off = swz((uint32_t)(r * 128 + pc4 * 8));
            *(uint2*)(smem + SM_QHI + off) = make_uint2(h0, h1);
            *(uint2*)(smem + SM_QLO + off) = make_uint2(l0, l1);
        }
    }

    const int g = lane >> 2;
    const int t = lane & 3;
    const int gq0 = q0 + wid * 16 + g;
    const int gq1 = gq0 + 8;
    const int wlo0 = (gq0 - WIN) > 0 ? (gq0 - WIN) : 0;
    const int whi0 = (gq0 + WIN) < (S_LEN - 1) ? (gq0 + WIN) : (S_LEN - 1);
    const int wlo1 = (gq1 - WIN) > 0 ? (gq1 - WIN) : 0;
    const int whi1 = (gq1 + WIN) < (S_LEN - 1) ? (gq1 + WIN) : (S_LEN - 1);
    const uint32_t rng0 = (uint32_t)(whi0 - wlo0);   // window size per row (tile-invariant)
    const uint32_t rng1 = (uint32_t)(whi1 - wlo1);

    float oc[8][4];
    #pragma unroll
    for (int i = 0; i < 8; i++)
        #pragma unroll
        for (int j = 0; j < 4; j++) oc[i][j] = 0.0f;
    float ls0 = 0.0f, ls1 = 0.0f;

    // ldmatrix addressing (lane-dependent, loop-invariant)
    const int qa_row  = wid * 16 + (lane & 15);
    const int qa_dsel = ((lane >> 4) & 1) * 16;
    const int kb_key  = (lane & 7) + ((lane & 16) ? 8 : 0);
    const int kb_dsel = (lane & 8) ? 16 : 0;
    const int vb_key  = (lane & 7) + ((lane & 8) ? 8 : 0);
    const int vb_dsel = (lane & 16) ? 16 : 0;

    for (int kt = 0; kt < NKT; kt++) {
        const int kbase = q0 - WIN + kt * KT;
        const int kt4 = kt * 4;      // 16-key group base index (0..19)

        __syncthreads();

        // ---- load K (bf16 hi/lo) and V (fp16 hi/lo) tiles, swizzled [key][dim] ----
        #pragma unroll
        for (int i = 0; i < 8; i++) {
            const int r = r0 + i * 8;
            const int gk = kbase + r;
            float4 xk = make_float4(0.f, 0.f, 0.f, 0.f);
            float4 xv = make_float4(0.f, 0.f, 0.f, 0.f);
            if (gk >= 0 && gk < S_LEN) {
                xk = *(const float4*)(K + base + (size_t)gk * rs + pc4 * 4);
                xv = *(const float4*)(V + base + (size_t)gk * rs + pc4 * 4);
            }
            const uint32_t off = swz((uint32_t)(r * 128 + pc4 * 8));
            uint32_t h0, l0, h1, l1;
            split_bf(xk.x, xk.y, h0, l0);
            split_bf(xk.z, xk.w, h1, l1);
            *(uint2*)(smem + SM_KHI + off) = make_uint2(h0, h1);
            *(uint2*)(smem + SM_KLO + off) = make_uint2(l0, l1);
            split_h2(xv.x, xv.y, h0, l0);
            split_h2(xv.z, xv.w, h1, l1);
            *(uint2*)(smem + SM_VHI + off) = make_uint2(h0, h1);
            *(uint2*)(smem + SM_VLO + off) = make_uint2(l0, l1);
        }
        __syncthreads();

        // ---- QK^T: S[16q x 64k], 3-way bf16 split, skip out-of-window 16-key groups ----
        float sc[8][4];
        #pragma unroll
        for (int i = 0; i < 8; i++)
            #pragma unroll
            for (int j = 0; j < 4; j++) sc[i][j] = 0.0f;

        #pragma unroll
        for (int ks = 0; ks < 4; ks++) {
            uint32_t qh[4], ql[4];
            const uint32_t qoff = swz((uint32_t)(qa_row * 128 + ks * 32 + qa_dsel));
            ldsm4(sb + SM_QHI + qoff, qh);
            ldsm4(sb + SM_QLO + qoff, ql);
            #pragma unroll
            for (int ng = 0; ng < 4; ng++) {
                const int g16 = kt4 + ng;
                if (g16 < wid || g16 > wid + 16) continue;   // warp-uniform skip
                const uint32_t off = swz((uint32_t)((ng * 16 + kb_key) * 128 + ks * 32 + kb_dsel));
                uint32_t bh[4], bl[4];
                ldsm4(sb + SM_KHI + off, bh);
                ldsm4(sb + SM_KLO + off, bl);
                mma_bf16(sc[2 * ng],     qh, bh[0], bh[1]);
                mma_bf16(sc[2 * ng],     qh, bl[0], bl[1]);
                mma_bf16(sc[2 * ng],     ql, bh[0], bh[1]);
                mma_bf16(sc[2 * ng + 1], qh, bh[2], bh[3]);
                mma_bf16(sc[2 * ng + 1], qh, bl[2], bl[3]);
                mma_bf16(sc[2 * ng + 1], ql, bh[2], bh[3]);
            }
        }

        // ---- per 16-key group: mask + exp2 + pack P(fp16) + PV (2-term) ----
        const int klo0 = wlo0 - kbase;
        const int klo1 = wlo1 - kbase;
        #pragma unroll
        for (int s = 0; s < 4; s++) {
            const int g16 = kt4 + s;
            if (g16 < wid || g16 > wid + 16) continue;       // warp-uniform skip

            const int ia = s * 16 + 2 * t;       // first c-half key offsets
            const int ib = ia + 8;               // second c-half
            float p[8];
            // row0 (gq0): c-frag regs [0],[1] of both nt groups
            p[0] = ((uint32_t)(ia - klo0)     <= rng0) ? ex2(sc[2*s][0])   : 0.0f;
            p[1] = ((uint32_t)(ia + 1 - klo0) <= rng0) ? ex2(sc[2*s][1])   : 0.0f;
            p[2] = ((uint32_t)(ia - klo1)     <= rng1) ? ex2(sc[2*s][2])   : 0.0f;
            p[3] = ((uint32_t)(ia + 1 - klo1) <= rng1) ? ex2(sc[2*s][3])   : 0.0f;
            p[4] = ((uint32_t)(ib - klo0)     <= rng0) ? ex2(sc[2*s+1][0]) : 0.0f;
            p[5] = ((uint32_t)(ib + 1 - klo0) <= rng0) ? ex2(sc[2*s+1][1]) : 0.0f;
            p[6] = ((uint32_t)(ib - klo1)     <= rng1) ? ex2(sc[2*s+1][2]) : 0.0f;
            p[7] = ((uint32_t)(ib + 1 - klo1) <= rng1) ? ex2(sc[2*s+1][3]) : 0.0f;
            ls0 += p[0] + p[1] + p[4] + p[5];
            ls1 += p[2] + p[3] + p[6] + p[7];

            uint32_t phi[4];
            phi[0] = pack_h2(p[0], p[1]);
            phi[1] = pack_h2(p[2], p[3]);
            phi[2] = pack_h2(p[4], p[5]);
            phi[3] = pack_h2(p[6], p[7]);

            #pragma unroll
            for (int dg = 0; dg < 4; dg++) {
                const uint32_t off = swz((uint32_t)((s * 16 + vb_key) * 128 + dg * 32 + vb_dsel));
                uint32_t vh[4], vl[4];
                ldsm4t(sb + SM_VHI + off, vh);
                ldsm4t(sb + SM_VLO + off, vl);
                mma_f16(oc[2 * dg],     phi, vh[0], vh[1]);
                mma_f16(oc[2 * dg],     phi, vl[0], vl[1]);
                mma_f16(oc[2 * dg + 1], phi, vh[2], vh[3]);
                mma_f16(oc[2 * dg + 1], phi, vl[2], vl[3]);
            }
        }
    }

    // ---- reduce lsum across the quad ----
    ls0 += __shfl_xor_sync(0xFFFFFFFF, ls0, 1);
    ls0 += __shfl_xor_sync(0xFFFFFFFF, ls0, 2);
    ls1 += __shfl_xor_sync(0xFFFFFFFF, ls1, 1);
    ls1 += __shfl_xor_sync(0xFFFFFFFF, ls1, 2);
    const float inv0 = 1.0f / ls0;
    const float inv1 = 1.0f / ls1;

    // ---- write output: O[b][gq][n][d] ----
    float* dst0 = O + base + (size_t)gq0 * rs;
    float* dst1 = O + base + (size_t)gq1 * rs;
    #pragma unroll
    for (int nt = 0; nt < 8; nt++) {
        const int d = nt * 8 + 2 * t;
        *(float2*)(dst0 + d) = make_float2(oc[nt][0] * inv0, oc[nt][1] * inv0);
        *(float2*)(dst1 + d) = make_float2(oc[nt][2] * inv1, oc[nt][3] * inv1);
    }
}

extern "C" void kernel_launch(void* const* d_in, const int* in_sizes, int n_in,
                              void* d_out, int out_size) {
    const float* q = (const float*)d_in[0];
    const float* k = (const float*)d_in[1];
    const float* v = (const float*)d_in[2];
    float* out = (float*)d_out;

    const int b = in_sizes[0] / (S_LEN * NHEAD * HD);

    dim3 grid(S_LEN / QT, b * NHEAD);
    wattn_mma_kernel<<<grid, 128>>>(q, k, v, out);
}

// round 7
// speedup vs baseline: 8.9932x; 1.1151x over previous
#include <cuda_runtime.h>
#include <cuda_bf16.h>
#include <cuda_fp16.h>
#include <cstdint>

#define S_LEN 4096
#define NHEAD 16
#define HD    64
#define WIN   128
#define QT    64
#define KT    64
#define NKT   5        // (QT + 2*WIN) / KT

// ---- static smem byte offsets (tiles: 64 rows x 128 bytes, XOR-swizzled) ----
#define SM_QHI 0
#define SM_QLO 8192
#define SM_KHI 16384
#define SM_KLO 24576
#define SM_V   32768
#define SM_TOTAL 40960

// 0.125 * log2(e)
#define QSCALE 0.1803368801111204f
#define ONES_H2 0x3C003C00u

__device__ __forceinline__ uint32_t swz(uint32_t o) {
    return o ^ (((o >> 7) & 7u) << 4);
}
__device__ __forceinline__ uint32_t smem_u32(const void* p) {
    uint32_t a;
    asm("{ .reg .u64 t; cvta.to.shared.u64 t, %1; cvt.u32.u64 %0, t; }" : "=r"(a) : "l"(p));
    return a;
}
__device__ __forceinline__ void ldsm4(uint32_t addr, uint32_t* r) {
    asm volatile("ldmatrix.sync.aligned.m8n8.x4.shared.b16 {%0,%1,%2,%3}, [%4];"
        : "=r"(r[0]), "=r"(r[1]), "=r"(r[2]), "=r"(r[3]) : "r"(addr));
}
__device__ __forceinline__ void ldsm4t(uint32_t addr, uint32_t* r) {
    asm volatile("ldmatrix.sync.aligned.m8n8.x4.trans.shared.b16 {%0,%1,%2,%3}, [%4];"
        : "=r"(r[0]), "=r"(r[1]), "=r"(r[2]), "=r"(r[3]) : "r"(addr));
}
__device__ __forceinline__ void mma_bf16(float* c, const uint32_t* a, uint32_t b0, uint32_t b1) {
    asm volatile("mma.sync.aligned.m16n8k16.row.col.f32.bf16.bf16.f32 "
        "{%0,%1,%2,%3}, {%4,%5,%6,%7}, {%8,%9}, {%0,%1,%2,%3};"
        : "+f"(c[0]), "+f"(c[1]), "+f"(c[2]), "+f"(c[3])
        : "r"(a[0]), "r"(a[1]), "r"(a[2]), "r"(a[3]), "r"(b0), "r"(b1));
}
__device__ __forceinline__ void mma_f16(float* c, const uint32_t* a, uint32_t b0, uint32_t b1) {
    asm volatile("mma.sync.aligned.m16n8k16.row.col.f32.f16.f16.f32 "
        "{%0,%1,%2,%3}, {%4,%5,%6,%7}, {%8,%9}, {%0,%1,%2,%3};"
        : "+f"(c[0]), "+f"(c[1]), "+f"(c[2]), "+f"(c[3])
        : "r"(a[0]), "r"(a[1]), "r"(a[2]), "r"(a[3]), "r"(b0), "r"(b1));
}
__device__ __forceinline__ uint32_t pack_bf(float lo, float hi) {
    uint32_t r;
    asm("cvt.rn.bf16x2.f32 %0, %1, %2;" : "=r"(r) : "f"(hi), "f"(lo));
    return r;
}
__device__ __forceinline__ void split_bf(float x0, float x1, uint32_t& h, uint32_t& l) {
    h = pack_bf(x0, x1);
    const float h0 = __uint_as_float(h << 16);
    const float h1 = __uint_as_float(h & 0xFFFF0000u);
    l = pack_bf(x0 - h0, x1 - h1);
}
__device__ __forceinline__ uint32_t pack_h2(float lo, float hi) {
    __half2 h = __floats2half2_rn(lo, hi);
    return *reinterpret_cast<uint32_t*>(&h);
}
__device__ __forceinline__ float ex2(float x) {
    float r;
    asm("ex2.approx.f32 %0, %1;" : "=f"(r) : "f"(x));
    return r;
}

__global__ void __launch_bounds__(128, 3)
wattn_mma_kernel(const float* __restrict__ Q, const float* __restrict__ K,
                 const float* __restrict__ V, float* __restrict__ O) {
    __shared__ char smem[SM_TOTAL];
    const uint32_t sb = smem_u32(smem);

    const int tid  = threadIdx.x;
    const int wid  = tid >> 5;
    const int lane = tid & 31;

    const int q0 = blockIdx.x * QT;
    const int b  = blockIdx.y >> 4;
    const int n  = blockIdx.y & 15;
    const size_t base = ((size_t)b * S_LEN * NHEAD + (size_t)n) * (size_t)HD;
    const int rs = NHEAD * HD;

    const int pc4 = tid & 15;        // dim-quad 0..15 (4 dims = 8 bytes)
    const int r0  = tid >> 4;        // row base 0..7

    // ---- load Q tile -> bf16 hi/lo, swizzled [row][dim], scaled by 0.125*log2e ----
    {
        #pragma unroll
        for (int i = 0; i < 8; i++) {
            const int r = r0 + i * 8;
            const float4 x = *(const float4*)(Q + base + (size_t)(q0 + r) * rs + pc4 * 4);
            uint32_t h0, l0, h1, l1;
            split_bf(x.x * QSCALE, x.y * QSCALE, h0, l0);
            split_bf(x.z * QSCALE, x.w * QSCALE, h1, l1);
            const uint32_t off = swz((uint32_t)(r * 128 + pc4 * 8));
            *(uint2*)(smem + SM_QHI + off) = make_uint2(h0, h1);
            *(uint2*)(smem + SM_QLO + off) = make_uint2(l0, l1);
        }
    }

    const int g = lane >> 2;
    const int t = lane & 3;
    const int gq0 = q0 + wid * 16 + g;
    const int gq1 = gq0 + 8;
    const int wlo0 = (gq0 - WIN) > 0 ? (gq0 - WIN) : 0;
    const int whi0 = (gq0 + WIN) < (S_LEN - 1) ? (gq0 + WIN) : (S_LEN - 1);
    const int wlo1 = (gq1 - WIN) > 0 ? (gq1 - WIN) : 0;
    const int whi1 = (gq1 + WIN) < (S_LEN - 1) ? (gq1 + WIN) : (S_LEN - 1);
    const uint32_t rng0 = (uint32_t)(whi0 - wlo0);
    const uint32_t rng1 = (uint32_t)(whi1 - wlo1);

    float oc[8][4];
    #pragma unroll
    for (int i = 0; i < 8; i++)
        #pragma unroll
        for (int j = 0; j < 4; j++) oc[i][j] = 0.0f;
    float lsc[4] = {0.0f, 0.0f, 0.0f, 0.0f};   // row-sum c-frag (cols duplicated)

    // ldmatrix addressing (lane-dependent, loop-invariant)
    const int qa_row  = wid * 16 + (lane & 15);
    const int qa_dsel = ((lane >> 4) & 1) * 16;
    const int kb_key  = (lane & 7) + ((lane & 16) ? 8 : 0);
    const int kb_dsel = (lane & 8) ? 16 : 0;
    const int vb_key  = (lane & 7) + ((lane & 8) ? 8 : 0);
    const int vb_dsel = (lane & 16) ? 16 : 0;

    for (int kt = 0; kt < NKT; kt++) {
        const int kbase = q0 - WIN + kt * KT;
        const int kt4 = kt * 4;      // 16-key group base index

        __syncthreads();

        // ---- load K (bf16 hi/lo) and V (fp16) tiles, swizzled [key][dim] ----
        #pragma unroll
        for (int i = 0; i < 8; i++) {
            const int r = r0 + i * 8;
            const int gk = kbase + r;
            float4 xk = make_float4(0.f, 0.f, 0.f, 0.f);
            float4 xv = make_float4(0.f, 0.f, 0.f, 0.f);
            if (gk >= 0 && gk < S_LEN) {
                xk = *(const float4*)(K + base + (size_t)gk * rs + pc4 * 4);
                xv = *(const float4*)(V + base + (size_t)gk * rs + pc4 * 4);
            }
            const uint32_t off = swz((uint32_t)(r * 128 + pc4 * 8));
            uint32_t h0, l0, h1, l1;
            split_bf(xk.x, xk.y, h0, l0);
            split_bf(xk.z, xk.w, h1, l1);
            *(uint2*)(smem + SM_KHI + off) = make_uint2(h0, h1);
            *(uint2*)(smem + SM_KLO + off) = make_uint2(l0, l1);
            *(uint2*)(smem + SM_V + off) =
                make_uint2(pack_h2(xv.x, xv.y), pack_h2(xv.z, xv.w));
        }
        __syncthreads();

        // ---- QK^T: S[16q x 64k], 3-way bf16 split, skip out-of-window groups ----
        float sc[8][4];
        #pragma unroll
        for (int i = 0; i < 8; i++)
            #pragma unroll
            for (int j = 0; j < 4; j++) sc[i][j] = 0.0f;

        #pragma unroll
        for (int ks = 0; ks < 4; ks++) {
            uint32_t qh[4], ql[4];
            const uint32_t qoff = swz((uint32_t)(qa_row * 128 + ks * 32 + qa_dsel));
            ldsm4(sb + SM_QHI + qoff, qh);
            ldsm4(sb + SM_QLO + qoff, ql);
            #pragma unroll
            for (int ng = 0; ng < 4; ng++) {
                const int g16 = kt4 + ng;
                if (g16 < wid || g16 > wid + 16) continue;   // warp-uniform skip
                const uint32_t off = swz((uint32_t)((ng * 16 + kb_key) * 128 + ks * 32 + kb_dsel));
                uint32_t bh[4], bl[4];
                ldsm4(sb + SM_KHI + off, bh);
                ldsm4(sb + SM_KLO + off, bl);
                mma_bf16(sc[2 * ng],     qh, bh[0], bh[1]);
                mma_bf16(sc[2 * ng],     qh, bl[0], bl[1]);
                mma_bf16(sc[2 * ng],     ql, bh[0], bh[1]);
                mma_bf16(sc[2 * ng + 1], qh, bh[2], bh[3]);
                mma_bf16(sc[2 * ng + 1], qh, bl[2], bl[3]);
                mma_bf16(sc[2 * ng + 1], ql, bh[2], bh[3]);
            }
        }

        // ---- per 16-key group: mask + exp2 + pack P(fp16) + lsum-MMA + PV ----
        const int klo0 = wlo0 - kbase;
        const int klo1 = wlo1 - kbase;
        #pragma unroll
        for (int s = 0; s < 4; s++) {
            const int g16 = kt4 + s;
            if (g16 < wid || g16 > wid + 16) continue;       // warp-uniform skip

            const int ia = s * 16 + 2 * t;
            const int ib = ia + 8;
            float p[8];
            p[0] = ((uint32_t)(ia - klo0)     <= rng0) ? ex2(sc[2*s][0])   : 0.0f;
            p[1] = ((uint32_t)(ia + 1 - klo0) <= rng0) ? ex2(sc[2*s][1])   : 0.0f;
            p[2] = ((uint32_t)(ia - klo1)     <= rng1) ? ex2(sc[2*s][2])   : 0.0f;
            p[3] = ((uint32_t)(ia + 1 - klo1) <= rng1) ? ex2(sc[2*s][3])   : 0.0f;
            p[4] = ((uint32_t)(ib - klo0)     <= rng0) ? ex2(sc[2*s+1][0]) : 0.0f;
            p[5] = ((uint32_t)(ib + 1 - klo0) <= rng0) ? ex2(sc[2*s+1][1]) : 0.0f;
            p[6] = ((uint32_t)(ib - klo1)     <= rng1) ? ex2(sc[2*s+1][2]) : 0.0f;
            p[7] = ((uint32_t)(ib + 1 - klo1) <= rng1) ? ex2(sc[2*s+1][3]) : 0.0f;

            uint32_t phi[4];
            phi[0] = pack_h2(p[0], p[1]);
            phi[1] = pack_h2(p[2], p[3]);
            phi[2] = pack_h2(p[4], p[5]);
            phi[3] = pack_h2(p[6], p[7]);

            // row sums: B = all-ones -> every c column holds sum_k p
            mma_f16(lsc, phi, ONES_H2, ONES_H2);

            #pragma unroll
            for (int dg = 0; dg < 4; dg++) {
                const uint32_t off = swz((uint32_t)((s * 16 + vb_key) * 128 + dg * 32 + vb_dsel));
                uint32_t vh[4];
                ldsm4t(sb + SM_V + off, vh);
                mma_f16(oc[2 * dg],     phi, vh[0], vh[1]);
                mma_f16(oc[2 * dg + 1], phi, vh[2], vh[3]);
            }
        }
    }

    const float inv0 = 1.0f / lsc[0];
    const float inv1 = 1.0f / lsc[2];

    // ---- write output: O[b][gq][n][d] ----
    float* dst0 = O + base + (size_t)gq0 * rs;
    float* dst1 = O + base + (size_t)gq1 * rs;
    #pragma unroll
    for (int nt = 0; nt < 8; nt++) {
        const int d = nt * 8 + 2 * t;
        *(float2*)(dst0 + d) = make_float2(oc[nt][0] * inv0, oc[nt][1] * inv0);
        *(float2*)(dst1 + d) = make_float2(oc[nt][2] * inv1, oc[nt][3] * inv1);
    }
}

extern "C" void kernel_launch(void* const* d_in, const int* in_sizes, int n_in,
                              void* d_out, int out_size) {
    const float* q = (const float*)d_in[0];
    const float* k = (const float*)d_in[1];
    const float* v = (const float*)d_in[2];
    float* out = (float*)d_out;

    const int b = in_sizes[0] / (S_LEN * NHEAD * HD);

    dim3 grid(S_LEN / QT, b * NHEAD);
    wattn_mma_kernel<<<grid, 128>>>(q, k, v, out);
}